// round 10
// baseline (speedup 1.0000x reference)
#include <cuda_runtime.h>
#include <cuda_bf16.h>
#include <math.h>
#include <stdint.h>

// Problem constants (fixed shapes)
#define T_TOK   16384
#define DMODEL  512
#define HDIM    1024
#define NEXP    8
#define NDISP   (T_TOK * 2)              // T * top_k
#define PAD_CAP (NDISP + NEXP * 128)     // per-expert padding to 128-row tiles
#define MAXTILES ((NDISP / 128) + NEXP)  // 264
#define NT1 (MAXTILES * 8)               // GEMM1 tasks (8 n-tiles)
#define NT2 (MAXTILES * 4)               // GEMM2 tasks (4 n-tiles)

// ---------------- scratch (device globals; no allocations) ----------------
__device__ float g_h[(size_t)PAD_CAP * HDIM];   // GEMM1 output (post-GELU)
__device__ float g_y[(size_t)PAD_CAP * DMODEL]; // GEMM2 output (pre-scaled)
__device__ float g_zero[DMODEL];                // zero row for padded gathers
__device__ int   g_row_disp[PAD_CAP];           // padded row -> dispatch idx (or -1)
__device__ float g_row_scale[PAD_CAP];          // gate score per padded row
__device__ int   g_dest_row[NDISP];             // dispatch idx -> padded row
__device__ int   g_expert_of[NDISP];
__device__ float g_scale_of[NDISP];
__device__ int   g_count[NEXP];
__device__ int   g_cursor[NEXP];
__device__ int   g_pad_off[NEXP];
__device__ int   g_tile_start[NEXP + 1];
__device__ int   g_task_ctr;
__device__ int   g_done[MAXTILES];

// ---------------- packed f32x2 helpers ----------------
#define FMA2(acc, a2, b2)                                              \
    asm("fma.rn.f32x2 %0, %1, %2, %0;" : "+l"(acc) : "l"(a2), "l"(b2))

#define UNPACK2F(xf, yf, src)                                          \
    do {                                                               \
        uint32_t u0_, u1_;                                             \
        asm("mov.b64 {%0, %1}, %2;" : "=r"(u0_), "=r"(u1_) : "l"(src));\
        xf = __uint_as_float(u0_);                                     \
        yf = __uint_as_float(u1_);                                     \
    } while (0)

// ---------------- init ----------------
__global__ void init_kernel() {
    int i = blockIdx.x * blockDim.x + threadIdx.x;
    if (i < PAD_CAP) { g_row_disp[i] = -1; g_row_scale[i] = 0.f; }
    if (i < NEXP)    { g_count[i] = 0; g_cursor[i] = 0; }
    if (i < MAXTILES) g_done[i] = 0;
    if (i == 0) g_task_ctr = 0;
}

// ---------------- gating: logits -> top2 -> softmax ----------------
__global__ void gate_kernel(const float* __restrict__ x,
                            const float* __restrict__ gw,
                            const float* __restrict__ gb) {
    int warp = threadIdx.x >> 5, lane = threadIdx.x & 31;
    int t = blockIdx.x * 8 + warp;
    if (t >= T_TOK) return;

    float acc[NEXP];
#pragma unroll
    for (int e = 0; e < NEXP; e++) acc[e] = 0.f;

    const float* xr = x + (size_t)t * DMODEL;
    for (int i = lane; i < DMODEL; i += 32) {
        float xv = xr[i];
        const float4* g4 = (const float4*)(gw + (size_t)i * NEXP);
        float4 a = g4[0], b = g4[1];
        acc[0] += xv * a.x; acc[1] += xv * a.y; acc[2] += xv * a.z; acc[3] += xv * a.w;
        acc[4] += xv * b.x; acc[5] += xv * b.y; acc[6] += xv * b.z; acc[7] += xv * b.w;
    }
#pragma unroll
    for (int e = 0; e < NEXP; e++) {
#pragma unroll
        for (int off = 16; off > 0; off >>= 1)
            acc[e] += __shfl_xor_sync(0xFFFFFFFFu, acc[e], off);
    }

    if (lane == 0) {
        float v0 = -1e30f, v1 = -1e30f; int i0 = 0, i1 = 0;
#pragma unroll
        for (int e = 0; e < NEXP; e++) {
            float v = acc[e] + gb[e];
            if (v > v0) { v1 = v0; i1 = i0; v0 = v; i0 = e; }
            else if (v > v1) { v1 = v; i1 = e; }
        }
        float ed = expf(v1 - v0);
        float inv = 1.f / (1.f + ed);
        g_expert_of[2 * t + 0] = i0; g_scale_of[2 * t + 0] = inv;
        g_expert_of[2 * t + 1] = i1; g_scale_of[2 * t + 1] = ed * inv;
        atomicAdd(&g_count[i0], 1);
        atomicAdd(&g_count[i1], 1);
    }
}

// ---------------- padded offsets ----------------
__global__ void offsets_kernel() {
    if (threadIdx.x == 0) {
        int off = 0, ts = 0;
        for (int e = 0; e < NEXP; e++) {
            g_pad_off[e] = off;
            g_tile_start[e] = ts;
            int tiles = (g_count[e] + 127) >> 7;
            ts += tiles;
            off += tiles * 128;
        }
        g_tile_start[NEXP] = ts;
    }
}

// ---------------- scatter dispatches into padded rows ----------------
__global__ void scatter_kernel() {
    int j = blockIdx.x * blockDim.x + threadIdx.x;
    if (j >= NDISP) return;
    int e = g_expert_of[j];
    int pos = atomicAdd(&g_cursor[e], 1);
    int r = g_pad_off[e] + pos;
    g_row_disp[r] = j;
    g_row_scale[r] = g_scale_of[j];
    g_dest_row[j] = r;
}

__device__ __forceinline__ float gelu_exact(float v) {
    return 0.5f * v * (1.f + erff(v * 0.70710678118654752440f));
}

// ---------------- GEMM tile body: 128x128x8, FMA2, dup-A smem, 3-stage ring ----------------
// As: [3][8][256] floats, dup pairs: As[s][kk][2r]=As[s][kk][2r+1]=A[r][kk]
// Bs: [3][8][128] floats, natural rows (pairs contiguous -> direct u64x2 reads)
template <int KDIM, int NLD, bool LAYER1>
__device__ __forceinline__ void gemm_tile_body(
    int row_base, int e, int n0,
    const float* __restrict__ X, const float* __restrict__ W,
    const float* __restrict__ Bv,
    float* As, float* Bs, const float** Aptr)
{
    const int tid = threadIdx.x;
    if (tid < 128) {
        if (LAYER1) {
            int j = g_row_disp[row_base + tid];
            Aptr[tid] = (j >= 0) ? (X + (size_t)(j >> 1) * KDIM) : g_zero;
        } else {
            Aptr[tid] = g_h + (size_t)(row_base + tid) * KDIM;
        }
    }
    __syncthreads();

    const float* Wb = W + (size_t)e * KDIM * NLD + n0;
    const int arow = tid >> 1, ahalf = tid & 1;
    const int brow = tid >> 5, bchunk = tid & 31;
    const float* aSrc = Aptr[arow] + ahalf * 4;
    const float* bSrc = Wb + (size_t)brow * NLD + bchunk * 4;
    const int tx = tid & 15, ty = tid >> 4;

    uint64_t acc[8][4];
#pragma unroll
    for (int i = 0; i < 8; i++)
#pragma unroll
        for (int jp = 0; jp < 4; jp++) acc[i][jp] = 0ull;

    const int KT = KDIM / 8;
    float4 aReg, bReg;

#define STORE_STAGE(sbuf)                                                         \
    do {                                                                          \
        float2 d_;                                                                \
        d_.x = aReg.x; d_.y = aReg.x;                                             \
        *(float2*)&As[((sbuf) * 8 + ahalf * 4 + 0) * 256 + 2 * arow] = d_;        \
        d_.x = aReg.y; d_.y = aReg.y;                                             \
        *(float2*)&As[((sbuf) * 8 + ahalf * 4 + 1) * 256 + 2 * arow] = d_;        \
        d_.x = aReg.z; d_.y = aReg.z;                                             \
        *(float2*)&As[((sbuf) * 8 + ahalf * 4 + 2) * 256 + 2 * arow] = d_;        \
        d_.x = aReg.w; d_.y = aReg.w;                                             \
        *(float2*)&As[((sbuf) * 8 + ahalf * 4 + 3) * 256 + 2 * arow] = d_;        \
        *(float4*)&Bs[((sbuf) * 8 + brow) * 128 + bchunk * 4] = bReg;             \
    } while (0)

    // prologue: fill stages 0 and 1
    aReg = *(const float4*)(aSrc);
    bReg = *(const float4*)(bSrc);
    STORE_STAGE(0);
    aReg = *(const float4*)(aSrc + 8);
    bReg = *(const float4*)(bSrc + (size_t)8 * NLD);
    STORE_STAGE(1);
    __syncthreads();

    int buf = 0, wstage = 2;
    for (int kt = 0; kt < KT; ++kt) {
        if (kt + 2 < KT) {
            aReg = *(const float4*)(aSrc + (kt + 2) * 8);
            bReg = *(const float4*)(bSrc + (size_t)(kt + 2) * 8 * NLD);
        }

#pragma unroll
        for (int kk = 0; kk < 8; ++kk) {
            const float* aRow = As + (buf * 8 + kk) * 256;
            const float* bRow = Bs + (buf * 8 + kk) * 128;
            ulonglong2 av0 = *(const ulonglong2*)(aRow + 8 * ty);
            ulonglong2 av1 = *(const ulonglong2*)(aRow + 8 * ty + 4);
            ulonglong2 av2 = *(const ulonglong2*)(aRow + 128 + 8 * ty);
            ulonglong2 av3 = *(const ulonglong2*)(aRow + 128 + 8 * ty + 4);
            ulonglong2 bv0 = *(const ulonglong2*)(bRow + tx * 4);
            ulonglong2 bv1 = *(const ulonglong2*)(bRow + 64 + tx * 4);

            FMA2(acc[0][0], av0.x, bv0.x); FMA2(acc[0][1], av0.x, bv0.y);
            FMA2(acc[0][2], av0.x, bv1.x); FMA2(acc[0][3], av0.x, bv1.y);
            FMA2(acc[1][0], av0.y, bv0.x); FMA2(acc[1][1], av0.y, bv0.y);
            FMA2(acc[1][2], av0.y, bv1.x); FMA2(acc[1][3], av0.y, bv1.y);
            FMA2(acc[2][0], av1.x, bv0.x); FMA2(acc[2][1], av1.x, bv0.y);
            FMA2(acc[2][2], av1.x, bv1.x); FMA2(acc[2][3], av1.x, bv1.y);
            FMA2(acc[3][0], av1.y, bv0.x); FMA2(acc[3][1], av1.y, bv0.y);
            FMA2(acc[3][2], av1.y, bv1.x); FMA2(acc[3][3], av1.y, bv1.y);
            FMA2(acc[4][0], av2.x, bv0.x); FMA2(acc[4][1], av2.x, bv0.y);
            FMA2(acc[4][2], av2.x, bv1.x); FMA2(acc[4][3], av2.x, bv1.y);
            FMA2(acc[5][0], av2.y, bv0.x); FMA2(acc[5][1], av2.y, bv0.y);
            FMA2(acc[5][2], av2.y, bv1.x); FMA2(acc[5][3], av2.y, bv1.y);
            FMA2(acc[6][0], av3.x, bv0.x); FMA2(acc[6][1], av3.x, bv0.y);
            FMA2(acc[6][2], av3.x, bv1.x); FMA2(acc[6][3], av3.x, bv1.y);
            FMA2(acc[7][0], av3.y, bv0.x); FMA2(acc[7][1], av3.y, bv0.y);
            FMA2(acc[7][2], av3.y, bv1.x); FMA2(acc[7][3], av3.y, bv1.y);
        }

        if (kt + 2 < KT) STORE_STAGE(wstage);
        __syncthreads();
        buf = (buf == 2) ? 0 : buf + 1;
        wstage = (wstage == 2) ? 0 : wstage + 1;
    }
#undef STORE_STAGE

    // ---------------- epilogue ----------------
    float bias[8];
#pragma unroll
    for (int j = 0; j < 4; j++) {
        bias[j]     = Bv[(size_t)e * NLD + n0 + tx * 4 + j];
        bias[j + 4] = Bv[(size_t)e * NLD + n0 + 64 + tx * 4 + j];
    }
#pragma unroll
    for (int ii = 0; ii < 8; ++ii) {
        int rloc = (ii < 4) ? (ty * 4 + ii) : (64 + ty * 4 + (ii - 4));
        int r = row_base + rloc;
        float c[8];
        UNPACK2F(c[0], c[1], acc[ii][0]);
        UNPACK2F(c[2], c[3], acc[ii][1]);
        UNPACK2F(c[4], c[5], acc[ii][2]);
        UNPACK2F(c[6], c[7], acc[ii][3]);
        if (LAYER1) {
            float* dst = g_h + (size_t)r * NLD + n0;
            float4 o0, o1;
            o0.x = gelu_exact(c[0] + bias[0]);
            o0.y = gelu_exact(c[1] + bias[1]);
            o0.z = gelu_exact(c[2] + bias[2]);
            o0.w = gelu_exact(c[3] + bias[3]);
            o1.x = gelu_exact(c[4] + bias[4]);
            o1.y = gelu_exact(c[5] + bias[5]);
            o1.z = gelu_exact(c[6] + bias[6]);
            o1.w = gelu_exact(c[7] + bias[7]);
            *(float4*)(dst + tx * 4) = o0;
            *(float4*)(dst + 64 + tx * 4) = o1;
        } else {
            float s = g_row_scale[r];
            float* dst = g_y + (size_t)r * NLD + n0;
            float4 o0, o1;
            o0.x = (c[0] + bias[0]) * s;
            o0.y = (c[1] + bias[1]) * s;
            o0.z = (c[2] + bias[2]) * s;
            o0.w = (c[3] + bias[3]) * s;
            o1.x = (c[4] + bias[4]) * s;
            o1.y = (c[5] + bias[5]) * s;
            o1.z = (c[6] + bias[6]) * s;
            o1.w = (c[7] + bias[7]) * s;
            *(float4*)(dst + tx * 4) = o0;
            *(float4*)(dst + 64 + tx * 4) = o1;
        }
    }
}

// ---------------- fused persistent GEMM1+GEMM2 kernel ----------------
__global__ __launch_bounds__(256, 2) void fused_gemm_kernel(
    const float* __restrict__ x,
    const float* __restrict__ w1, const float* __restrict__ b1,
    const float* __restrict__ w2, const float* __restrict__ b2)
{
    __shared__ __align__(16) float As[3 * 8 * 256];
    __shared__ __align__(16) float Bs[3 * 8 * 128];
    __shared__ const float* Aptr[128];
    __shared__ int s_task;

    for (;;) {
        __syncthreads();   // smem reuse safety + previous task complete
        if (threadIdx.x == 0) s_task = atomicAdd(&g_task_ctr, 1);
        __syncthreads();
        int task = s_task;
        if (task >= NT1 + NT2) return;

        int ts_end = g_tile_start[NEXP];

        if (task < NT1) {
            // GEMM1 tile
            int rt = task >> 3;
            int n0 = (task & 7) * 128;
            if (rt >= ts_end) continue;
            int e = 0;
            while (e < NEXP - 1 && g_tile_start[e + 1] <= rt) e++;
            int row_base = g_pad_off[e] + (rt - g_tile_start[e]) * 128;
            gemm_tile_body<DMODEL, HDIM, true>(row_base, e, n0, x, w1, b1, As, Bs, Aptr);
            __threadfence();
            __syncthreads();
            if (threadIdx.x == 0) atomicAdd(&g_done[rt], 1);
        } else {
            // GEMM2 tile (waits for its row-tile's 8 GEMM1 tiles)
            int t2 = task - NT1;
            int rt = t2 >> 2;
            int n0 = (t2 & 3) * 128;
            if (rt >= ts_end) continue;
            if (threadIdx.x == 0) {
                while (*(volatile int*)&g_done[rt] < 8) __nanosleep(64);
                __threadfence();
            }
            __syncthreads();
            int e = 0;
            while (e < NEXP - 1 && g_tile_start[e + 1] <= rt) e++;
            int row_base = g_pad_off[e] + (rt - g_tile_start[e]) * 128;
            gemm_tile_body<HDIM, DMODEL, false>(row_base, e, n0, nullptr, w2, b2, As, Bs, Aptr);
        }
    }
}

// ---------------- combine: out[t] = y[row(t,0)] + y[row(t,1)] ----------------
__global__ void combine_kernel(float* __restrict__ out) {
    int t = blockIdx.x;
    int r0 = g_dest_row[2 * t + 0];
    int r1 = g_dest_row[2 * t + 1];
    const float4* y0 = (const float4*)(g_y + (size_t)r0 * DMODEL);
    const float4* y1 = (const float4*)(g_y + (size_t)r1 * DMODEL);
    float4* o = (float4*)(out + (size_t)t * DMODEL);
    int i = threadIdx.x;  // 128 threads, 128 float4s per row
    float4 a = y0[i], b = y1[i];
    float4 r;
    r.x = a.x + b.x; r.y = a.y + b.y; r.z = a.z + b.z; r.w = a.w + b.w;
    o[i] = r;
}

// ---------------- launch ----------------
extern "C" void kernel_launch(void* const* d_in, const int* in_sizes, int n_in,
                              void* d_out, int out_size) {
    const float* x      = (const float*)d_in[0];
    const float* gate_w = (const float*)d_in[1];
    const float* gate_b = (const float*)d_in[2];
    const float* w1     = (const float*)d_in[3];
    const float* b1     = (const float*)d_in[4];
    const float* w2     = (const float*)d_in[5];
    const float* b2     = (const float*)d_in[6];
    float* out = (float*)d_out;

    init_kernel<<<(PAD_CAP + 255) / 256, 256>>>();
    gate_kernel<<<T_TOK / 8, 256>>>(x, gate_w, gate_b);
    offsets_kernel<<<1, 32>>>();
    scatter_kernel<<<NDISP / 256, 256>>>();
    fused_gemm_kernel<<<296, 256>>>(x, w1, b1, w2, b2);
    combine_kernel<<<T_TOK, 128>>>(out);
}

// round 11
// speedup vs baseline: 1.2473x; 1.2473x over previous
#include <cuda_runtime.h>
#include <cuda_bf16.h>
#include <math.h>
#include <stdint.h>

// Problem constants (fixed shapes)
#define T_TOK   16384
#define DMODEL  512
#define HDIM    1024
#define NEXP    8
#define NDISP   (T_TOK * 2)              // T * top_k
#define PAD_CAP (NDISP + NEXP * 128)     // per-expert padding to 128-row tiles
#define MAXTILES ((NDISP / 128) + NEXP)  // 264
#define NT1 (MAXTILES * 8)               // GEMM1 tasks (8 n-tiles)
#define NT2 (MAXTILES * 4)               // GEMM2 tasks (4 n-tiles)

// ---------------- scratch (device globals; no allocations) ----------------
__device__ float g_h[(size_t)PAD_CAP * HDIM];   // GEMM1 output (post-GELU)
__device__ float g_y[(size_t)PAD_CAP * DMODEL]; // GEMM2 output (pre-scaled)
__device__ float g_zero[DMODEL];                // zero row for padded gathers
__device__ int   g_row_disp[PAD_CAP];           // padded row -> dispatch idx (or -1)
__device__ float g_row_scale[PAD_CAP];          // gate score per padded row
__device__ int   g_dest_row[NDISP];             // dispatch idx -> padded row
__device__ int   g_expert_of[NDISP];
__device__ float g_scale_of[NDISP];
__device__ int   g_count[NEXP];
__device__ int   g_cursor[NEXP];
__device__ int   g_pad_off[NEXP];
__device__ int   g_tile_start[NEXP + 1];
__device__ int   g_task_ctr;
__device__ int   g_done[MAXTILES];

// ---------------- packed f32x2 helpers ----------------
#define PACKDUP(dst, xf)                                               \
    asm("mov.b64 %0, {%1, %1};" : "=l"(dst) : "r"(__float_as_uint(xf)))

#define FMA2(acc, a2, b2)                                              \
    asm("fma.rn.f32x2 %0, %1, %2, %0;" : "+l"(acc) : "l"(a2), "l"(b2))

#define UNPACK2F(xf, yf, src)                                          \
    do {                                                               \
        uint32_t u0_, u1_;                                             \
        asm("mov.b64 {%0, %1}, %2;" : "=r"(u0_), "=r"(u1_) : "l"(src));\
        xf = __uint_as_float(u0_);                                     \
        yf = __uint_as_float(u1_);                                     \
    } while (0)

// ---------------- init ----------------
__global__ void init_kernel() {
    int i = blockIdx.x * blockDim.x + threadIdx.x;
    if (i < PAD_CAP) { g_row_disp[i] = -1; g_row_scale[i] = 0.f; }
    if (i < NEXP)    { g_count[i] = 0; g_cursor[i] = 0; }
    if (i < MAXTILES) g_done[i] = 0;
    if (i == 0) g_task_ctr = 0;
}

// ---------------- gating: logits -> top2 -> softmax ----------------
__global__ void gate_kernel(const float* __restrict__ x,
                            const float* __restrict__ gw,
                            const float* __restrict__ gb) {
    int warp = threadIdx.x >> 5, lane = threadIdx.x & 31;
    int t = blockIdx.x * 8 + warp;
    if (t >= T_TOK) return;

    float acc[NEXP];
#pragma unroll
    for (int e = 0; e < NEXP; e++) acc[e] = 0.f;

    const float* xr = x + (size_t)t * DMODEL;
    for (int i = lane; i < DMODEL; i += 32) {
        float xv = xr[i];
        const float4* g4 = (const float4*)(gw + (size_t)i * NEXP);
        float4 a = g4[0], b = g4[1];
        acc[0] += xv * a.x; acc[1] += xv * a.y; acc[2] += xv * a.z; acc[3] += xv * a.w;
        acc[4] += xv * b.x; acc[5] += xv * b.y; acc[6] += xv * b.z; acc[7] += xv * b.w;
    }
#pragma unroll
    for (int e = 0; e < NEXP; e++) {
#pragma unroll
        for (int off = 16; off > 0; off >>= 1)
            acc[e] += __shfl_xor_sync(0xFFFFFFFFu, acc[e], off);
    }

    if (lane == 0) {
        float v0 = -1e30f, v1 = -1e30f; int i0 = 0, i1 = 0;
#pragma unroll
        for (int e = 0; e < NEXP; e++) {
            float v = acc[e] + gb[e];
            if (v > v0) { v1 = v0; i1 = i0; v0 = v; i0 = e; }
            else if (v > v1) { v1 = v; i1 = e; }
        }
        float ed = expf(v1 - v0);
        float inv = 1.f / (1.f + ed);
        g_expert_of[2 * t + 0] = i0; g_scale_of[2 * t + 0] = inv;
        g_expert_of[2 * t + 1] = i1; g_scale_of[2 * t + 1] = ed * inv;
        atomicAdd(&g_count[i0], 1);
        atomicAdd(&g_count[i1], 1);
    }
}

// ---------------- padded offsets ----------------
__global__ void offsets_kernel() {
    if (threadIdx.x == 0) {
        int off = 0, ts = 0;
        for (int e = 0; e < NEXP; e++) {
            g_pad_off[e] = off;
            g_tile_start[e] = ts;
            int tiles = (g_count[e] + 127) >> 7;
            ts += tiles;
            off += tiles * 128;
        }
        g_tile_start[NEXP] = ts;
    }
}

// ---------------- scatter dispatches into padded rows ----------------
__global__ void scatter_kernel() {
    int j = blockIdx.x * blockDim.x + threadIdx.x;
    if (j >= NDISP) return;
    int e = g_expert_of[j];
    int pos = atomicAdd(&g_cursor[e], 1);
    int r = g_pad_off[e] + pos;
    g_row_disp[r] = j;
    g_row_scale[r] = g_scale_of[j];
    g_dest_row[j] = r;
}

__device__ __forceinline__ float gelu_exact(float v) {
    return 0.5f * v * (1.f + erff(v * 0.70710678118654752440f));
}

// ---------------- GEMM tile body (R9-identical): 128x128x8, FMA2, 3-stage ring ----------------
// As: [3][8][128] floats, column-major per kk (A[r][kk] at As[kk][r])
// Bs: [3][8][128] floats, natural rows (pairs contiguous -> direct u64x2 reads)
template <int KDIM, int NLD, bool LAYER1>
__device__ __forceinline__ void gemm_tile_body(
    int row_base, int e, int n0,
    const float* __restrict__ X, const float* __restrict__ W,
    const float* __restrict__ Bv,
    float* As, float* Bs, const float** Aptr)
{
    const int tid = threadIdx.x;
    if (tid < 128) {
        if (LAYER1) {
            int j = g_row_disp[row_base + tid];
            Aptr[tid] = (j >= 0) ? (X + (size_t)(j >> 1) * KDIM) : g_zero;
        } else {
            Aptr[tid] = g_h + (size_t)(row_base + tid) * KDIM;
        }
    }
    __syncthreads();

    const float* Wb = W + (size_t)e * KDIM * NLD + n0;
    const int arow = tid >> 1, ahalf = tid & 1;
    const int brow = tid >> 5, bchunk = tid & 31;
    const float* aSrc = Aptr[arow] + ahalf * 4;
    const float* bSrc = Wb + (size_t)brow * NLD + bchunk * 4;
    const int tx = tid & 15, ty = tid >> 4;

    uint64_t acc[8][4];
#pragma unroll
    for (int i = 0; i < 8; i++)
#pragma unroll
        for (int jp = 0; jp < 4; jp++) acc[i][jp] = 0ull;

    const int KT = KDIM / 8;
    float4 aReg, bReg;

#define STORE_STAGE(sbuf)                                                   \
    do {                                                                    \
        As[((sbuf) * 8 + ahalf * 4 + 0) * 128 + arow] = aReg.x;             \
        As[((sbuf) * 8 + ahalf * 4 + 1) * 128 + arow] = aReg.y;             \
        As[((sbuf) * 8 + ahalf * 4 + 2) * 128 + arow] = aReg.z;             \
        As[((sbuf) * 8 + ahalf * 4 + 3) * 128 + arow] = aReg.w;             \
        *(float4*)&Bs[((sbuf) * 8 + brow) * 128 + bchunk * 4] = bReg;       \
    } while (0)

    // prologue: fill stages 0 and 1
    aReg = *(const float4*)(aSrc);
    bReg = *(const float4*)(bSrc);
    STORE_STAGE(0);
    aReg = *(const float4*)(aSrc + 8);
    bReg = *(const float4*)(bSrc + (size_t)8 * NLD);
    STORE_STAGE(1);
    __syncthreads();

    int buf = 0, wstage = 2;
    for (int kt = 0; kt < KT; ++kt) {
        if (kt + 2 < KT) {
            aReg = *(const float4*)(aSrc + (kt + 2) * 8);
            bReg = *(const float4*)(bSrc + (size_t)(kt + 2) * 8 * NLD);
        }

#pragma unroll
        for (int kk = 0; kk < 8; ++kk) {
            const float* aRow = As + (buf * 8 + kk) * 128;
            const float* bRow = Bs + (buf * 8 + kk) * 128;
            float4 a0 = *(const float4*)(aRow + ty * 4);
            float4 a1 = *(const float4*)(aRow + 64 + ty * 4);
            ulonglong2 bv0 = *(const ulonglong2*)(bRow + tx * 4);
            ulonglong2 bv1 = *(const ulonglong2*)(bRow + 64 + tx * 4);

            uint64_t aa;
            PACKDUP(aa, a0.x);
            FMA2(acc[0][0], aa, bv0.x); FMA2(acc[0][1], aa, bv0.y);
            FMA2(acc[0][2], aa, bv1.x); FMA2(acc[0][3], aa, bv1.y);
            PACKDUP(aa, a0.y);
            FMA2(acc[1][0], aa, bv0.x); FMA2(acc[1][1], aa, bv0.y);
            FMA2(acc[1][2], aa, bv1.x); FMA2(acc[1][3], aa, bv1.y);
            PACKDUP(aa, a0.z);
            FMA2(acc[2][0], aa, bv0.x); FMA2(acc[2][1], aa, bv0.y);
            FMA2(acc[2][2], aa, bv1.x); FMA2(acc[2][3], aa, bv1.y);
            PACKDUP(aa, a0.w);
            FMA2(acc[3][0], aa, bv0.x); FMA2(acc[3][1], aa, bv0.y);
            FMA2(acc[3][2], aa, bv1.x); FMA2(acc[3][3], aa, bv1.y);
            PACKDUP(aa, a1.x);
            FMA2(acc[4][0], aa, bv0.x); FMA2(acc[4][1], aa, bv0.y);
            FMA2(acc[4][2], aa, bv1.x); FMA2(acc[4][3], aa, bv1.y);
            PACKDUP(aa, a1.y);
            FMA2(acc[5][0], aa, bv0.x); FMA2(acc[5][1], aa, bv0.y);
            FMA2(acc[5][2], aa, bv1.x); FMA2(acc[5][3], aa, bv1.y);
            PACKDUP(aa, a1.z);
            FMA2(acc[6][0], aa, bv0.x); FMA2(acc[6][1], aa, bv0.y);
            FMA2(acc[6][2], aa, bv1.x); FMA2(acc[6][3], aa, bv1.y);
            PACKDUP(aa, a1.w);
            FMA2(acc[7][0], aa, bv0.x); FMA2(acc[7][1], aa, bv0.y);
            FMA2(acc[7][2], aa, bv1.x); FMA2(acc[7][3], aa, bv1.y);
        }

        if (kt + 2 < KT) STORE_STAGE(wstage);
        __syncthreads();
        buf = (buf == 2) ? 0 : buf + 1;
        wstage = (wstage == 2) ? 0 : wstage + 1;
    }
#undef STORE_STAGE

    // ---------------- epilogue ----------------
    float bias[8];
#pragma unroll
    for (int j = 0; j < 4; j++) {
        bias[j]     = Bv[(size_t)e * NLD + n0 + tx * 4 + j];
        bias[j + 4] = Bv[(size_t)e * NLD + n0 + 64 + tx * 4 + j];
    }
#pragma unroll
    for (int ii = 0; ii < 8; ++ii) {
        int rloc = (ii < 4) ? (ty * 4 + ii) : (64 + ty * 4 + (ii - 4));
        int r = row_base + rloc;
        float c[8];
        UNPACK2F(c[0], c[1], acc[ii][0]);
        UNPACK2F(c[2], c[3], acc[ii][1]);
        UNPACK2F(c[4], c[5], acc[ii][2]);
        UNPACK2F(c[6], c[7], acc[ii][3]);
        if (LAYER1) {
            float* dst = g_h + (size_t)r * NLD + n0;
            float4 o0, o1;
            o0.x = gelu_exact(c[0] + bias[0]);
            o0.y = gelu_exact(c[1] + bias[1]);
            o0.z = gelu_exact(c[2] + bias[2]);
            o0.w = gelu_exact(c[3] + bias[3]);
            o1.x = gelu_exact(c[4] + bias[4]);
            o1.y = gelu_exact(c[5] + bias[5]);
            o1.z = gelu_exact(c[6] + bias[6]);
            o1.w = gelu_exact(c[7] + bias[7]);
            *(float4*)(dst + tx * 4) = o0;
            *(float4*)(dst + 64 + tx * 4) = o1;
        } else {
            float s = g_row_scale[r];
            float* dst = g_y + (size_t)r * NLD + n0;
            float4 o0, o1;
            o0.x = (c[0] + bias[0]) * s;
            o0.y = (c[1] + bias[1]) * s;
            o0.z = (c[2] + bias[2]) * s;
            o0.w = (c[3] + bias[3]) * s;
            o1.x = (c[4] + bias[4]) * s;
            o1.y = (c[5] + bias[5]) * s;
            o1.z = (c[6] + bias[6]) * s;
            o1.w = (c[7] + bias[7]) * s;
            *(float4*)(dst + tx * 4) = o0;
            *(float4*)(dst + 64 + tx * 4) = o1;
        }
    }
}

// ---------------- fused persistent GEMM1+GEMM2 kernel ----------------
__global__ __launch_bounds__(256, 2) void fused_gemm_kernel(
    const float* __restrict__ x,
    const float* __restrict__ w1, const float* __restrict__ b1,
    const float* __restrict__ w2, const float* __restrict__ b2)
{
    __shared__ __align__(16) float As[3 * 8 * 128];
    __shared__ __align__(16) float Bs[3 * 8 * 128];
    __shared__ const float* Aptr[128];
    __shared__ int s_task;

    for (;;) {
        __syncthreads();   // smem reuse safety + previous task complete
        if (threadIdx.x == 0) s_task = atomicAdd(&g_task_ctr, 1);
        __syncthreads();
        int task = s_task;
        if (task >= NT1 + NT2) return;

        int ts_end = g_tile_start[NEXP];

        if (task < NT1) {
            // GEMM1 tile
            int rt = task >> 3;
            int n0 = (task & 7) * 128;
            if (rt >= ts_end) continue;
            int e = 0;
            while (e < NEXP - 1 && g_tile_start[e + 1] <= rt) e++;
            int row_base = g_pad_off[e] + (rt - g_tile_start[e]) * 128;
            gemm_tile_body<DMODEL, HDIM, true>(row_base, e, n0, x, w1, b1, As, Bs, Aptr);
            __threadfence();
            __syncthreads();
            if (threadIdx.x == 0) atomicAdd(&g_done[rt], 1);
        } else {
            // GEMM2 tile (waits for its row-tile's 8 GEMM1 tiles)
            int t2 = task - NT1;
            int rt = t2 >> 2;
            int n0 = (t2 & 3) * 128;
            if (rt >= ts_end) continue;
            if (threadIdx.x == 0) {
                while (*(volatile int*)&g_done[rt] < 8) __nanosleep(64);
                __threadfence();
            }
            __syncthreads();
            int e = 0;
            while (e < NEXP - 1 && g_tile_start[e + 1] <= rt) e++;
            int row_base = g_pad_off[e] + (rt - g_tile_start[e]) * 128;
            gemm_tile_body<HDIM, DMODEL, false>(row_base, e, n0, nullptr, w2, b2, As, Bs, Aptr);
        }
    }
}

// ---------------- combine: out[t] = y[row(t,0)] + y[row(t,1)] ----------------
__global__ void combine_kernel(float* __restrict__ out) {
    int t = blockIdx.x;
    int r0 = g_dest_row[2 * t + 0];
    int r1 = g_dest_row[2 * t + 1];
    const float4* y0 = (const float4*)(g_y + (size_t)r0 * DMODEL);
    const float4* y1 = (const float4*)(g_y + (size_t)r1 * DMODEL);
    float4* o = (float4*)(out + (size_t)t * DMODEL);
    int i = threadIdx.x;  // 128 threads, 128 float4s per row
    float4 a = y0[i], b = y1[i];
    float4 r;
    r.x = a.x + b.x; r.y = a.y + b.y; r.z = a.z + b.z; r.w = a.w + b.w;
    o[i] = r;
}

// ---------------- launch ----------------
extern "C" void kernel_launch(void* const* d_in, const int* in_sizes, int n_in,
                              void* d_out, int out_size) {
    const float* x      = (const float*)d_in[0];
    const float* gate_w = (const float*)d_in[1];
    const float* gate_b = (const float*)d_in[2];
    const float* w1     = (const float*)d_in[3];
    const float* b1     = (const float*)d_in[4];
    const float* w2     = (const float*)d_in[5];
    const float* b2     = (const float*)d_in[6];
    float* out = (float*)d_out;

    init_kernel<<<(PAD_CAP + 255) / 256, 256>>>();
    gate_kernel<<<T_TOK / 8, 256>>>(x, gate_w, gate_b);
    offsets_kernel<<<1, 32>>>();
    scatter_kernel<<<NDISP / 256, 256>>>();
    fused_gemm_kernel<<<296, 256>>>(x, w1, b1, w2, b2);
    combine_kernel<<<T_TOK, 128>>>(out);
}

// round 12
// speedup vs baseline: 1.2775x; 1.0243x over previous
#include <cuda_runtime.h>
#include <cuda_bf16.h>
#include <math.h>
#include <stdint.h>

// Problem constants (fixed shapes)
#define T_TOK   16384
#define DMODEL  512
#define HDIM    1024
#define NEXP    8
#define NDISP   (T_TOK * 2)              // T * top_k
#define PAD_CAP (NDISP + NEXP * 128)     // per-expert padding to 128-row tiles
#define MAXTILES ((NDISP / 128) + NEXP)  // 264
#define NT1 (MAXTILES * 8)               // GEMM1 tasks (8 n-tiles)
#define NT2 (MAXTILES * 4)               // GEMM2 tasks (4 n-tiles)

// ---------------- scratch (device globals; no allocations) ----------------
__device__ float g_h[(size_t)PAD_CAP * HDIM];   // GEMM1 output (post-GELU)
__device__ float g_zero[DMODEL];                // zero row for padded gathers
__device__ int   g_row_disp[PAD_CAP];           // padded row -> dispatch idx (or -1)
__device__ float g_row_scale[PAD_CAP];          // gate score per padded row
__device__ int   g_expert_of[NDISP];
__device__ float g_scale_of[NDISP];
__device__ int   g_count[NEXP];
__device__ int   g_cursor[NEXP];
__device__ int   g_pad_off[NEXP];
__device__ int   g_tile_start[NEXP + 1];
__device__ int   g_task_ctr;
__device__ int   g_done[MAXTILES];

// ---------------- packed f32x2 helpers ----------------
#define PACKDUP(dst, xf)                                               \
    asm("mov.b64 %0, {%1, %1};" : "=l"(dst) : "r"(__float_as_uint(xf)))

#define FMA2(acc, a2, b2)                                              \
    asm("fma.rn.f32x2 %0, %1, %2, %0;" : "+l"(acc) : "l"(a2), "l"(b2))

#define UNPACK2F(xf, yf, src)                                          \
    do {                                                               \
        uint32_t u0_, u1_;                                             \
        asm("mov.b64 {%0, %1}, %2;" : "=r"(u0_), "=r"(u1_) : "l"(src));\
        xf = __uint_as_float(u0_);                                     \
        yf = __uint_as_float(u1_);                                     \
    } while (0)

// ---------------- init: reset control state + zero output ----------------
__global__ void init_kernel(float* __restrict__ out) {
    int i = blockIdx.x * blockDim.x + threadIdx.x;
    if (i < PAD_CAP) { g_row_disp[i] = -1; g_row_scale[i] = 0.f; }
    if (i < NEXP)    { g_count[i] = 0; g_cursor[i] = 0; }
    if (i < MAXTILES) g_done[i] = 0;
    if (i == 0) g_task_ctr = 0;
    // zero out[T_TOK * DMODEL]: 2,097,152 float4s
    if (i < (T_TOK * DMODEL) / 4) {
        ((float4*)out)[i] = make_float4(0.f, 0.f, 0.f, 0.f);
    }
}

// ---------------- gating: logits -> top2 -> softmax (block-aggregated counts) ----------------
__global__ void gate_kernel(const float* __restrict__ x,
                            const float* __restrict__ gw,
                            const float* __restrict__ gb) {
    __shared__ int s_cnt[NEXP];
    int warp = threadIdx.x >> 5, lane = threadIdx.x & 31;
    int t = blockIdx.x * 8 + warp;   // grid = T_TOK/8 blocks of 256 -> exact

    if (threadIdx.x < NEXP) s_cnt[threadIdx.x] = 0;
    __syncthreads();

    float acc[NEXP];
#pragma unroll
    for (int e = 0; e < NEXP; e++) acc[e] = 0.f;

    const float* xr = x + (size_t)t * DMODEL;
    for (int i = lane; i < DMODEL; i += 32) {
        float xv = xr[i];
        const float4* g4 = (const float4*)(gw + (size_t)i * NEXP);
        float4 a = g4[0], b = g4[1];
        acc[0] += xv * a.x; acc[1] += xv * a.y; acc[2] += xv * a.z; acc[3] += xv * a.w;
        acc[4] += xv * b.x; acc[5] += xv * b.y; acc[6] += xv * b.z; acc[7] += xv * b.w;
    }
#pragma unroll
    for (int e = 0; e < NEXP; e++) {
#pragma unroll
        for (int off = 16; off > 0; off >>= 1)
            acc[e] += __shfl_xor_sync(0xFFFFFFFFu, acc[e], off);
    }

    if (lane == 0) {
        float v0 = -1e30f, v1 = -1e30f; int i0 = 0, i1 = 0;
#pragma unroll
        for (int e = 0; e < NEXP; e++) {
            float v = acc[e] + gb[e];
            if (v > v0) { v1 = v0; i1 = i0; v0 = v; i0 = e; }
            else if (v > v1) { v1 = v; i1 = e; }
        }
        float ed = expf(v1 - v0);
        float inv = 1.f / (1.f + ed);
        g_expert_of[2 * t + 0] = i0; g_scale_of[2 * t + 0] = inv;
        g_expert_of[2 * t + 1] = i1; g_scale_of[2 * t + 1] = ed * inv;
        atomicAdd(&s_cnt[i0], 1);
        atomicAdd(&s_cnt[i1], 1);
    }
    __syncthreads();
    if (threadIdx.x < NEXP && s_cnt[threadIdx.x] > 0)
        atomicAdd(&g_count[threadIdx.x], s_cnt[threadIdx.x]);
}

// ---------------- padded offsets ----------------
__global__ void offsets_kernel() {
    if (threadIdx.x == 0) {
        int off = 0, ts = 0;
        for (int e = 0; e < NEXP; e++) {
            g_pad_off[e] = off;
            g_tile_start[e] = ts;
            int tiles = (g_count[e] + 127) >> 7;
            ts += tiles;
            off += tiles * 128;
        }
        g_tile_start[NEXP] = ts;
    }
}

// ---------------- scatter dispatches into padded rows (block-aggregated) ----------------
__global__ void scatter_kernel() {
    __shared__ int s_cnt[NEXP];
    __shared__ int s_base[NEXP];
    int j = blockIdx.x * blockDim.x + threadIdx.x;  // exact: NDISP/256 blocks

    if (threadIdx.x < NEXP) s_cnt[threadIdx.x] = 0;
    __syncthreads();

    int e = g_expert_of[j];
    int lpos = atomicAdd(&s_cnt[e], 1);
    __syncthreads();

    if (threadIdx.x < NEXP) {
        int c = s_cnt[threadIdx.x];
        s_base[threadIdx.x] = (c > 0) ? atomicAdd(&g_cursor[threadIdx.x], c) : 0;
    }
    __syncthreads();

    int r = g_pad_off[e] + s_base[e] + lpos;
    g_row_disp[r] = j;
    g_row_scale[r] = g_scale_of[j];
}

__device__ __forceinline__ float gelu_exact(float v) {
    return 0.5f * v * (1.f + erff(v * 0.70710678118654752440f));
}

// ---------------- GEMM tile body (R11-identical loop): 128x128x8, FMA2, 3-stage ring ----------------
// LAYER2 epilogue atomically accumulates into out[token] (combine fused).
template <int KDIM, int NLD, bool LAYER1>
__device__ __forceinline__ void gemm_tile_body(
    int row_base, int e, int n0,
    const float* __restrict__ X, const float* __restrict__ W,
    const float* __restrict__ Bv, float* __restrict__ out,
    float* As, float* Bs, const float** Aptr)
{
    const int tid = threadIdx.x;
    if (tid < 128) {
        if (LAYER1) {
            int j = g_row_disp[row_base + tid];
            Aptr[tid] = (j >= 0) ? (X + (size_t)(j >> 1) * KDIM) : g_zero;
        } else {
            Aptr[tid] = g_h + (size_t)(row_base + tid) * KDIM;
        }
    }
    __syncthreads();

    const float* Wb = W + (size_t)e * KDIM * NLD + n0;
    const int arow = tid >> 1, ahalf = tid & 1;
    const int brow = tid >> 5, bchunk = tid & 31;
    const float* aSrc = Aptr[arow] + ahalf * 4;
    const float* bSrc = Wb + (size_t)brow * NLD + bchunk * 4;
    const int tx = tid & 15, ty = tid >> 4;

    uint64_t acc[8][4];
#pragma unroll
    for (int i = 0; i < 8; i++)
#pragma unroll
        for (int jp = 0; jp < 4; jp++) acc[i][jp] = 0ull;

    const int KT = KDIM / 8;
    float4 aReg, bReg;

#define STORE_STAGE(sbuf)                                                   \
    do {                                                                    \
        As[((sbuf) * 8 + ahalf * 4 + 0) * 128 + arow] = aReg.x;             \
        As[((sbuf) * 8 + ahalf * 4 + 1) * 128 + arow] = aReg.y;             \
        As[((sbuf) * 8 + ahalf * 4 + 2) * 128 + arow] = aReg.z;             \
        As[((sbuf) * 8 + ahalf * 4 + 3) * 128 + arow] = aReg.w;             \
        *(float4*)&Bs[((sbuf) * 8 + brow) * 128 + bchunk * 4] = bReg;       \
    } while (0)

    // prologue: fill stages 0 and 1
    aReg = *(const float4*)(aSrc);
    bReg = *(const float4*)(bSrc);
    STORE_STAGE(0);
    aReg = *(const float4*)(aSrc + 8);
    bReg = *(const float4*)(bSrc + (size_t)8 * NLD);
    STORE_STAGE(1);
    __syncthreads();

    int buf = 0, wstage = 2;
    for (int kt = 0; kt < KT; ++kt) {
        if (kt + 2 < KT) {
            aReg = *(const float4*)(aSrc + (kt + 2) * 8);
            bReg = *(const float4*)(bSrc + (size_t)(kt + 2) * 8 * NLD);
        }

#pragma unroll
        for (int kk = 0; kk < 8; ++kk) {
            const float* aRow = As + (buf * 8 + kk) * 128;
            const float* bRow = Bs + (buf * 8 + kk) * 128;
            float4 a0 = *(const float4*)(aRow + ty * 4);
            float4 a1 = *(const float4*)(aRow + 64 + ty * 4);
            ulonglong2 bv0 = *(const ulonglong2*)(bRow + tx * 4);
            ulonglong2 bv1 = *(const ulonglong2*)(bRow + 64 + tx * 4);

            uint64_t aa;
            PACKDUP(aa, a0.x);
            FMA2(acc[0][0], aa, bv0.x); FMA2(acc[0][1], aa, bv0.y);
            FMA2(acc[0][2], aa, bv1.x); FMA2(acc[0][3], aa, bv1.y);
            PACKDUP(aa, a0.y);
            FMA2(acc[1][0], aa, bv0.x); FMA2(acc[1][1], aa, bv0.y);
            FMA2(acc[1][2], aa, bv1.x); FMA2(acc[1][3], aa, bv1.y);
            PACKDUP(aa, a0.z);
            FMA2(acc[2][0], aa, bv0.x); FMA2(acc[2][1], aa, bv0.y);
            FMA2(acc[2][2], aa, bv1.x); FMA2(acc[2][3], aa, bv1.y);
            PACKDUP(aa, a0.w);
            FMA2(acc[3][0], aa, bv0.x); FMA2(acc[3][1], aa, bv0.y);
            FMA2(acc[3][2], aa, bv1.x); FMA2(acc[3][3], aa, bv1.y);
            PACKDUP(aa, a1.x);
            FMA2(acc[4][0], aa, bv0.x); FMA2(acc[4][1], aa, bv0.y);
            FMA2(acc[4][2], aa, bv1.x); FMA2(acc[4][3], aa, bv1.y);
            PACKDUP(aa, a1.y);
            FMA2(acc[5][0], aa, bv0.x); FMA2(acc[5][1], aa, bv0.y);
            FMA2(acc[5][2], aa, bv1.x); FMA2(acc[5][3], aa, bv1.y);
            PACKDUP(aa, a1.z);
            FMA2(acc[6][0], aa, bv0.x); FMA2(acc[6][1], aa, bv0.y);
            FMA2(acc[6][2], aa, bv1.x); FMA2(acc[6][3], aa, bv1.y);
            PACKDUP(aa, a1.w);
            FMA2(acc[7][0], aa, bv0.x); FMA2(acc[7][1], aa, bv0.y);
            FMA2(acc[7][2], aa, bv1.x); FMA2(acc[7][3], aa, bv1.y);
        }

        if (kt + 2 < KT) STORE_STAGE(wstage);
        __syncthreads();
        buf = (buf == 2) ? 0 : buf + 1;
        wstage = (wstage == 2) ? 0 : wstage + 1;
    }
#undef STORE_STAGE

    // ---------------- epilogue ----------------
    float bias[8];
#pragma unroll
    for (int j = 0; j < 4; j++) {
        bias[j]     = Bv[(size_t)e * NLD + n0 + tx * 4 + j];
        bias[j + 4] = Bv[(size_t)e * NLD + n0 + 64 + tx * 4 + j];
    }
#pragma unroll
    for (int ii = 0; ii < 8; ++ii) {
        int rloc = (ii < 4) ? (ty * 4 + ii) : (64 + ty * 4 + (ii - 4));
        int r = row_base + rloc;
        float c[8];
        UNPACK2F(c[0], c[1], acc[ii][0]);
        UNPACK2F(c[2], c[3], acc[ii][1]);
        UNPACK2F(c[4], c[5], acc[ii][2]);
        UNPACK2F(c[6], c[7], acc[ii][3]);
        if (LAYER1) {
            float* dst = g_h + (size_t)r * NLD + n0;
            float4 o0, o1;
            o0.x = gelu_exact(c[0] + bias[0]);
            o0.y = gelu_exact(c[1] + bias[1]);
            o0.z = gelu_exact(c[2] + bias[2]);
            o0.w = gelu_exact(c[3] + bias[3]);
            o1.x = gelu_exact(c[4] + bias[4]);
            o1.y = gelu_exact(c[5] + bias[5]);
            o1.z = gelu_exact(c[6] + bias[6]);
            o1.w = gelu_exact(c[7] + bias[7]);
            *(float4*)(dst + tx * 4) = o0;
            *(float4*)(dst + 64 + tx * 4) = o1;
        } else {
            int j = g_row_disp[r];
            if (j >= 0) {
                float s = g_row_scale[r];
                float* dst = out + (size_t)(j >> 1) * DMODEL + n0;
#pragma unroll
                for (int q = 0; q < 4; q++)
                    atomicAdd(dst + tx * 4 + q, (c[q] + bias[q]) * s);
#pragma unroll
                for (int q = 0; q < 4; q++)
                    atomicAdd(dst + 64 + tx * 4 + q, (c[4 + q] + bias[4 + q]) * s);
            }
        }
    }
}

// ---------------- fused persistent GEMM1+GEMM2 kernel ----------------
__global__ __launch_bounds__(256, 2) void fused_gemm_kernel(
    const float* __restrict__ x,
    const float* __restrict__ w1, const float* __restrict__ b1,
    const float* __restrict__ w2, const float* __restrict__ b2,
    float* __restrict__ out)
{
    __shared__ __align__(16) float As[3 * 8 * 128];
    __shared__ __align__(16) float Bs[3 * 8 * 128];
    __shared__ const float* Aptr[128];
    __shared__ int s_task;

    for (;;) {
        __syncthreads();   // smem reuse safety + previous task complete
        if (threadIdx.x == 0) s_task = atomicAdd(&g_task_ctr, 1);
        __syncthreads();
        int task = s_task;
        if (task >= NT1 + NT2) return;

        int ts_end = g_tile_start[NEXP];

        if (task < NT1) {
            // GEMM1 tile
            int rt = task >> 3;
            int n0 = (task & 7) * 128;
            if (rt >= ts_end) continue;
            int e = 0;
            while (e < NEXP - 1 && g_tile_start[e + 1] <= rt) e++;
            int row_base = g_pad_off[e] + (rt - g_tile_start[e]) * 128;
            gemm_tile_body<DMODEL, HDIM, true>(row_base, e, n0, x, w1, b1, out, As, Bs, Aptr);
            __threadfence();
            __syncthreads();
            if (threadIdx.x == 0) atomicAdd(&g_done[rt], 1);
        } else {
            // GEMM2 tile (waits for its row-tile's 8 GEMM1 tiles)
            int t2 = task - NT1;
            int rt = t2 >> 2;
            int n0 = (t2 & 3) * 128;
            if (rt >= ts_end) continue;
            if (threadIdx.x == 0) {
                while (*(volatile int*)&g_done[rt] < 8) __nanosleep(64);
                __threadfence();
            }
            __syncthreads();
            int e = 0;
            while (e < NEXP - 1 && g_tile_start[e + 1] <= rt) e++;
            int row_base = g_pad_off[e] + (rt - g_tile_start[e]) * 128;
            gemm_tile_body<HDIM, DMODEL, false>(row_base, e, n0, nullptr, w2, b2, out, As, Bs, Aptr);
        }
    }
}

// ---------------- launch ----------------
extern "C" void kernel_launch(void* const* d_in, const int* in_sizes, int n_in,
                              void* d_out, int out_size) {
    const float* x      = (const float*)d_in[0];
    const float* gate_w = (const float*)d_in[1];
    const float* gate_b = (const float*)d_in[2];
    const float* w1     = (const float*)d_in[3];
    const float* b1     = (const float*)d_in[4];
    const float* w2     = (const float*)d_in[5];
    const float* b2     = (const float*)d_in[6];
    float* out = (float*)d_out;

    init_kernel<<<(T_TOK * DMODEL / 4 + 255) / 256, 256>>>(out);
    gate_kernel<<<T_TOK / 8, 256>>>(x, gate_w, gate_b);
    offsets_kernel<<<1, 32>>>();
    scatter_kernel<<<NDISP / 256, 256>>>();
    fused_gemm_kernel<<<296, 256>>>(x, w1, b1, w2, b2, out);
}

// round 13
// speedup vs baseline: 1.3206x; 1.0337x over previous
#include <cuda_runtime.h>
#include <cuda_bf16.h>
#include <math.h>
#include <stdint.h>

// Problem constants (fixed shapes)
#define T_TOK   16384
#define DMODEL  512
#define HDIM    1024
#define NEXP    8
#define NDISP   (T_TOK * 2)              // T * top_k
#define PAD_CAP (NDISP + NEXP * 128)     // per-expert padding to 128-row tiles
#define MAXTILES ((NDISP / 128) + NEXP)  // 264
#define NT1 (MAXTILES * 8)               // GEMM1 tasks (8 n-tiles)
#define NT2 (MAXTILES * 4)               // GEMM2 tasks (4 n-tiles)

// ---------------- scratch (device globals; no allocations) ----------------
__device__ float g_h[(size_t)PAD_CAP * HDIM];   // GEMM1 output (post-GELU)
__device__ float g_zero[DMODEL];                // zero row for padded gathers
__device__ int   g_row_disp[PAD_CAP];           // padded row -> dispatch idx (or -1)
__device__ float g_row_scale[PAD_CAP];          // gate score per padded row
__device__ int   g_expert_of[NDISP];
__device__ float g_scale_of[NDISP];
__device__ int   g_count[NEXP];
__device__ int   g_cursor[NEXP];
__device__ int   g_pad_off[NEXP];
__device__ int   g_tile_start[NEXP + 1];
__device__ int   g_task_ctr;
__device__ int   g_done[MAXTILES];

// ---------------- packed f32x2 helpers ----------------
#define PACKDUP(dst, xf)                                               \
    asm("mov.b64 %0, {%1, %1};" : "=l"(dst) : "r"(__float_as_uint(xf)))

#define FMA2(acc, a2, b2)                                              \
    asm("fma.rn.f32x2 %0, %1, %2, %0;" : "+l"(acc) : "l"(a2), "l"(b2))

#define UNPACK2F(xf, yf, src)                                          \
    do {                                                               \
        uint32_t u0_, u1_;                                             \
        asm("mov.b64 {%0, %1}, %2;" : "=r"(u0_), "=r"(u1_) : "l"(src));\
        xf = __uint_as_float(u0_);                                     \
        yf = __uint_as_float(u1_);                                     \
    } while (0)

// ---------------- init: reset control state only ----------------
__global__ void init_kernel() {
    int i = blockIdx.x * blockDim.x + threadIdx.x;
    if (i < PAD_CAP) { g_row_disp[i] = -1; g_row_scale[i] = 0.f; }
    if (i < NEXP)    { g_count[i] = 0; g_cursor[i] = 0; }
    if (i < MAXTILES) g_done[i] = 0;
    if (i == 0) g_task_ctr = 0;
}

// ---------------- gating: logits -> top2 -> softmax; also zeroes out ----------------
__global__ void gate_kernel(const float* __restrict__ x,
                            const float* __restrict__ gw,
                            const float* __restrict__ gb,
                            float* __restrict__ out) {
    __shared__ int s_cnt[NEXP];
    int warp = threadIdx.x >> 5, lane = threadIdx.x & 31;
    int t = blockIdx.x * 8 + warp;   // grid = T_TOK/8 blocks of 256 -> exact

    // zero the output buffer (grid covers exactly: 2048 blocks * 256 thr * 4 float4)
    {
        size_t zi = (size_t)blockIdx.x * 256 + threadIdx.x;
        float4 z4 = make_float4(0.f, 0.f, 0.f, 0.f);
        float4* o4 = (float4*)out;
#pragma unroll
        for (int q = 0; q < 4; q++)
            o4[zi + (size_t)q * (T_TOK / 8 * 256)] = z4;
    }

    if (threadIdx.x < NEXP) s_cnt[threadIdx.x] = 0;
    __syncthreads();

    float acc[NEXP];
#pragma unroll
    for (int e = 0; e < NEXP; e++) acc[e] = 0.f;

    const float* xr = x + (size_t)t * DMODEL;
    for (int i = lane; i < DMODEL; i += 32) {
        float xv = xr[i];
        const float4* g4 = (const float4*)(gw + (size_t)i * NEXP);
        float4 a = g4[0], b = g4[1];
        acc[0] += xv * a.x; acc[1] += xv * a.y; acc[2] += xv * a.z; acc[3] += xv * a.w;
        acc[4] += xv * b.x; acc[5] += xv * b.y; acc[6] += xv * b.z; acc[7] += xv * b.w;
    }
#pragma unroll
    for (int e = 0; e < NEXP; e++) {
#pragma unroll
        for (int off = 16; off > 0; off >>= 1)
            acc[e] += __shfl_xor_sync(0xFFFFFFFFu, acc[e], off);
    }

    if (lane == 0) {
        float v0 = -1e30f, v1 = -1e30f; int i0 = 0, i1 = 0;
#pragma unroll
        for (int e = 0; e < NEXP; e++) {
            float v = acc[e] + gb[e];
            if (v > v0) { v1 = v0; i1 = i0; v0 = v; i0 = e; }
            else if (v > v1) { v1 = v; i1 = e; }
        }
        float ed = expf(v1 - v0);
        float inv = 1.f / (1.f + ed);
        g_expert_of[2 * t + 0] = i0; g_scale_of[2 * t + 0] = inv;
        g_expert_of[2 * t + 1] = i1; g_scale_of[2 * t + 1] = ed * inv;
        atomicAdd(&s_cnt[i0], 1);
        atomicAdd(&s_cnt[i1], 1);
    }
    __syncthreads();
    if (threadIdx.x < NEXP && s_cnt[threadIdx.x] > 0)
        atomicAdd(&g_count[threadIdx.x], s_cnt[threadIdx.x]);
}

// ---------------- padded offsets ----------------
__global__ void offsets_kernel() {
    if (threadIdx.x == 0) {
        int off = 0, ts = 0;
        for (int e = 0; e < NEXP; e++) {
            g_pad_off[e] = off;
            g_tile_start[e] = ts;
            int tiles = (g_count[e] + 127) >> 7;
            ts += tiles;
            off += tiles * 128;
        }
        g_tile_start[NEXP] = ts;
    }
}

// ---------------- scatter dispatches into padded rows (block-aggregated) ----------------
__global__ void scatter_kernel() {
    __shared__ int s_cnt[NEXP];
    __shared__ int s_base[NEXP];
    int j = blockIdx.x * blockDim.x + threadIdx.x;  // exact: NDISP/256 blocks

    if (threadIdx.x < NEXP) s_cnt[threadIdx.x] = 0;
    __syncthreads();

    int e = g_expert_of[j];
    int lpos = atomicAdd(&s_cnt[e], 1);
    __syncthreads();

    if (threadIdx.x < NEXP) {
        int c = s_cnt[threadIdx.x];
        s_base[threadIdx.x] = (c > 0) ? atomicAdd(&g_cursor[threadIdx.x], c) : 0;
    }
    __syncthreads();

    int r = g_pad_off[e] + s_base[e] + lpos;
    g_row_disp[r] = j;
    g_row_scale[r] = g_scale_of[j];
}

__device__ __forceinline__ float gelu_exact(float v) {
    return 0.5f * v * (1.f + erff(v * 0.70710678118654752440f));
}

// ---------------- GEMM tile body: 128x128x8, FMA2, 4-stage ring, sync per 2 kt ----------------
// As: [4][8][128] floats, column-major per kk (A[r][kk] at As[kk][r])
// Bs: [4][8][128] floats, natural rows (pairs contiguous -> direct u64x2 reads)
// Hazard window: between syncs (even kt e .. e+1), reads hit stages {e,e+1}%4,
// writes hit {e+2,e+3}%4 — disjoint for any warp skew inside the window.
template <int KDIM, int NLD, bool LAYER1>
__device__ __forceinline__ void gemm_tile_body(
    int row_base, int e, int n0,
    const float* __restrict__ X, const float* __restrict__ W,
    const float* __restrict__ Bv, float* __restrict__ out,
    float* As, float* Bs, const float** Aptr)
{
    const int tid = threadIdx.x;
    if (tid < 128) {
        if (LAYER1) {
            int j = g_row_disp[row_base + tid];
            Aptr[tid] = (j >= 0) ? (X + (size_t)(j >> 1) * KDIM) : g_zero;
        } else {
            Aptr[tid] = g_h + (size_t)(row_base + tid) * KDIM;
        }
    }
    __syncthreads();

    const float* Wb = W + (size_t)e * KDIM * NLD + n0;
    const int arow = tid >> 1, ahalf = tid & 1;
    const int brow = tid >> 5, bchunk = tid & 31;
    const float* aSrc = Aptr[arow] + ahalf * 4;
    const float* bSrc = Wb + (size_t)brow * NLD + bchunk * 4;
    const int tx = tid & 15, ty = tid >> 4;

    uint64_t acc[8][4];
#pragma unroll
    for (int i = 0; i < 8; i++)
#pragma unroll
        for (int jp = 0; jp < 4; jp++) acc[i][jp] = 0ull;

    const int KT = KDIM / 8;
    float4 aReg, bReg;

#define STORE_STAGE(sbuf)                                                   \
    do {                                                                    \
        As[((sbuf) * 8 + ahalf * 4 + 0) * 128 + arow] = aReg.x;             \
        As[((sbuf) * 8 + ahalf * 4 + 1) * 128 + arow] = aReg.y;             \
        As[((sbuf) * 8 + ahalf * 4 + 2) * 128 + arow] = aReg.z;             \
        As[((sbuf) * 8 + ahalf * 4 + 3) * 128 + arow] = aReg.w;             \
        *(float4*)&Bs[((sbuf) * 8 + brow) * 128 + bchunk * 4] = bReg;       \
    } while (0)

    // prologue: fill stages 0 and 1
    aReg = *(const float4*)(aSrc);
    bReg = *(const float4*)(bSrc);
    STORE_STAGE(0);
    aReg = *(const float4*)(aSrc + 8);
    bReg = *(const float4*)(bSrc + (size_t)8 * NLD);
    STORE_STAGE(1);
    __syncthreads();

    for (int kt = 0; kt < KT; ++kt) {
        if (kt > 0 && (kt & 1) == 0) __syncthreads();   // even-kt boundary

        if (kt + 2 < KT) {
            aReg = *(const float4*)(aSrc + (kt + 2) * 8);
            bReg = *(const float4*)(bSrc + (size_t)(kt + 2) * 8 * NLD);
        }

        const int buf = kt & 3;
#pragma unroll
        for (int kk = 0; kk < 8; ++kk) {
            const float* aRow = As + (buf * 8 + kk) * 128;
            const float* bRow = Bs + (buf * 8 + kk) * 128;
            float4 a0 = *(const float4*)(aRow + ty * 4);
            float4 a1 = *(const float4*)(aRow + 64 + ty * 4);
            ulonglong2 bv0 = *(const ulonglong2*)(bRow + tx * 4);
            ulonglong2 bv1 = *(const ulonglong2*)(bRow + 64 + tx * 4);

            uint64_t aa;
            PACKDUP(aa, a0.x);
            FMA2(acc[0][0], aa, bv0.x); FMA2(acc[0][1], aa, bv0.y);
            FMA2(acc[0][2], aa, bv1.x); FMA2(acc[0][3], aa, bv1.y);
            PACKDUP(aa, a0.y);
            FMA2(acc[1][0], aa, bv0.x); FMA2(acc[1][1], aa, bv0.y);
            FMA2(acc[1][2], aa, bv1.x); FMA2(acc[1][3], aa, bv1.y);
            PACKDUP(aa, a0.z);
            FMA2(acc[2][0], aa, bv0.x); FMA2(acc[2][1], aa, bv0.y);
            FMA2(acc[2][2], aa, bv1.x); FMA2(acc[2][3], aa, bv1.y);
            PACKDUP(aa, a0.w);
            FMA2(acc[3][0], aa, bv0.x); FMA2(acc[3][1], aa, bv0.y);
            FMA2(acc[3][2], aa, bv1.x); FMA2(acc[3][3], aa, bv1.y);
            PACKDUP(aa, a1.x);
            FMA2(acc[4][0], aa, bv0.x); FMA2(acc[4][1], aa, bv0.y);
            FMA2(acc[4][2], aa, bv1.x); FMA2(acc[4][3], aa, bv1.y);
            PACKDUP(aa, a1.y);
            FMA2(acc[5][0], aa, bv0.x); FMA2(acc[5][1], aa, bv0.y);
            FMA2(acc[5][2], aa, bv1.x); FMA2(acc[5][3], aa, bv1.y);
            PACKDUP(aa, a1.z);
            FMA2(acc[6][0], aa, bv0.x); FMA2(acc[6][1], aa, bv0.y);
            FMA2(acc[6][2], aa, bv1.x); FMA2(acc[6][3], aa, bv1.y);
            PACKDUP(aa, a1.w);
            FMA2(acc[7][0], aa, bv0.x); FMA2(acc[7][1], aa, bv0.y);
            FMA2(acc[7][2], aa, bv1.x); FMA2(acc[7][3], aa, bv1.y);
        }

        if (kt + 2 < KT) STORE_STAGE((kt + 2) & 3);
    }
#undef STORE_STAGE

    // make final-stage reads complete before epilogue overwrites shared state next task
    __syncthreads();

    // ---------------- epilogue ----------------
    float bias[8];
#pragma unroll
    for (int j = 0; j < 4; j++) {
        bias[j]     = Bv[(size_t)e * NLD + n0 + tx * 4 + j];
        bias[j + 4] = Bv[(size_t)e * NLD + n0 + 64 + tx * 4 + j];
    }
#pragma unroll
    for (int ii = 0; ii < 8; ++ii) {
        int rloc = (ii < 4) ? (ty * 4 + ii) : (64 + ty * 4 + (ii - 4));
        int r = row_base + rloc;
        float c[8];
        UNPACK2F(c[0], c[1], acc[ii][0]);
        UNPACK2F(c[2], c[3], acc[ii][1]);
        UNPACK2F(c[4], c[5], acc[ii][2]);
        UNPACK2F(c[6], c[7], acc[ii][3]);
        if (LAYER1) {
            float* dst = g_h + (size_t)r * NLD + n0;
            float4 o0, o1;
            o0.x = gelu_exact(c[0] + bias[0]);
            o0.y = gelu_exact(c[1] + bias[1]);
            o0.z = gelu_exact(c[2] + bias[2]);
            o0.w = gelu_exact(c[3] + bias[3]);
            o1.x = gelu_exact(c[4] + bias[4]);
            o1.y = gelu_exact(c[5] + bias[5]);
            o1.z = gelu_exact(c[6] + bias[6]);
            o1.w = gelu_exact(c[7] + bias[7]);
            *(float4*)(dst + tx * 4) = o0;
            *(float4*)(dst + 64 + tx * 4) = o1;
        } else {
            int j = g_row_disp[r];
            if (j >= 0) {
                float s = g_row_scale[r];
                float* dst = out + (size_t)(j >> 1) * DMODEL + n0;
#pragma unroll
                for (int q = 0; q < 4; q++)
                    atomicAdd(dst + tx * 4 + q, (c[q] + bias[q]) * s);
#pragma unroll
                for (int q = 0; q < 4; q++)
                    atomicAdd(dst + 64 + tx * 4 + q, (c[4 + q] + bias[4 + q]) * s);
            }
        }
    }
}

// ---------------- fused persistent GEMM1+GEMM2 kernel ----------------
__global__ __launch_bounds__(256, 2) void fused_gemm_kernel(
    const float* __restrict__ x,
    const float* __restrict__ w1, const float* __restrict__ b1,
    const float* __restrict__ w2, const float* __restrict__ b2,
    float* __restrict__ out)
{
    __shared__ __align__(16) float As[4 * 8 * 128];
    __shared__ __align__(16) float Bs[4 * 8 * 128];
    __shared__ const float* Aptr[128];
    __shared__ int s_task;

    for (;;) {
        __syncthreads();   // smem reuse safety + previous task complete
        if (threadIdx.x == 0) s_task = atomicAdd(&g_task_ctr, 1);
        __syncthreads();
        int task = s_task;
        if (task >= NT1 + NT2) return;

        int ts_end = g_tile_start[NEXP];

        if (task < NT1) {
            // GEMM1 tile
            int rt = task >> 3;
            int n0 = (task & 7) * 128;
            if (rt >= ts_end) continue;
            int e = 0;
            while (e < NEXP - 1 && g_tile_start[e + 1] <= rt) e++;
            int row_base = g_pad_off[e] + (rt - g_tile_start[e]) * 128;
            gemm_tile_body<DMODEL, HDIM, true>(row_base, e, n0, x, w1, b1, out, As, Bs, Aptr);
            __threadfence();
            __syncthreads();
            if (threadIdx.x == 0) atomicAdd(&g_done[rt], 1);
        } else {
            // GEMM2 tile (waits for its row-tile's 8 GEMM1 tiles)
            int t2 = task - NT1;
            int rt = t2 >> 2;
            int n0 = (t2 & 3) * 128;
            if (rt >= ts_end) continue;
            if (threadIdx.x == 0) {
                while (*(volatile int*)&g_done[rt] < 8) __nanosleep(64);
                __threadfence();
            }
            __syncthreads();
            int e = 0;
            while (e < NEXP - 1 && g_tile_start[e + 1] <= rt) e++;
            int row_base = g_pad_off[e] + (rt - g_tile_start[e]) * 128;
            gemm_tile_body<HDIM, DMODEL, false>(row_base, e, n0, nullptr, w2, b2, out, As, Bs, Aptr);
        }
    }
}

// ---------------- launch ----------------
extern "C" void kernel_launch(void* const* d_in, const int* in_sizes, int n_in,
                              void* d_out, int out_size) {
    const float* x      = (const float*)d_in[0];
    const float* gate_w = (const float*)d_in[1];
    const float* gate_b = (const float*)d_in[2];
    const float* w1     = (const float*)d_in[3];
    const float* b1     = (const float*)d_in[4];
    const float* w2     = (const float*)d_in[5];
    const float* b2     = (const float*)d_in[6];
    float* out = (float*)d_out;

    init_kernel<<<(PAD_CAP + 255) / 256, 256>>>();
    gate_kernel<<<T_TOK / 8, 256>>>(x, gate_w, gate_b, out);
    offsets_kernel<<<1, 32>>>();
    scatter_kernel<<<NDISP / 256, 256>>>();
    fused_gemm_kernel<<<296, 256>>>(x, w1, b1, w2, b2, out);
}